// round 1
// baseline (speedup 1.0000x reference)
#include <cuda_runtime.h>

// L2LossWithRebalancing — GB300 sm_103a
// Strategy: argmin over centers == argmax of (256*ca*t0 + 256*cb*t1 - |c|^2).
// Pack center index into the low 9 mantissa bits of the score; running fmaxf
// tracks best (score, index) in one register. f32x2 packed FMA processes 2
// pixels per instruction. Deterministic 2-stage reduction.

#define K_REAL 313
#define KP 320                     // padded (unroll-friendly, fits 9 index bits)
#define NPIX (16 * 256 * 256)      // 1048576
#define CH_STRIDE 65536            // H*W
#define IMG_STRIDE (2 * 65536)     // 2 channels
#define PX_PER_THREAD 8
#define THREADS 256
#define NBLOCKS (NPIX / (PX_PER_THREAD * THREADS))   // 512

__device__ ulonglong2          g_cA[KP];        // {cx,cx}, {cy,cy} packed
__device__ unsigned long long  g_cB[KP];        // {bias,bias} packed
__device__ float               g_w[KP];         // class weight per center
__device__ float               g_partials[NBLOCKS];

__device__ __forceinline__ unsigned long long pack2f(float lo, float hi) {
    unsigned long long r;
    asm("mov.b64 %0, {%1, %2};" : "=l"(r) : "f"(lo), "f"(hi));
    return r;
}

__device__ __forceinline__ unsigned long long ffma2(unsigned long long a,
                                                    unsigned long long b,
                                                    unsigned long long c) {
    unsigned long long d;
    asm("fma.rn.f32x2 %0, %1, %2, %3;" : "=l"(d) : "l"(a), "l"(b), "l"(c));
    return d;
}

__global__ void prep_kernel(const float* __restrict__ centers,
                            const float* __restrict__ cw) {
    int k = threadIdx.x;
    if (k >= KP) return;
    float cx = 0.f, cy = 0.f, bias = -1e30f, w = 0.f;
    if (k < K_REAL) {
        float ca = centers[2 * k];
        float cb = centers[2 * k + 1];
        cx   = 256.f * ca;                 // 2 * (128*t) * ca  ->  256*ca * t
        cy   = 256.f * cb;
        bias = -(ca * ca + cb * cb);
        w    = cw[k];
    }
    g_cA[k].x = pack2f(cx, cx);
    g_cA[k].y = pack2f(cy, cy);
    g_cB[k]   = pack2f(bias, bias);
    g_w[k]    = w;
}

__global__ __launch_bounds__(THREADS)
void loss_kernel(const float* __restrict__ pred,
                 const float* __restrict__ target) {
    __shared__ ulonglong2         sA[KP];
    __shared__ unsigned long long sB[KP];
    __shared__ float              sw_[KP];
    __shared__ float              sred[THREADS / 32];

    const int t = threadIdx.x;
    for (int i = t; i < KP; i += THREADS) {
        sA[i]  = g_cA[i];
        sB[i]  = g_cB[i];
        sw_[i] = g_w[i];
    }
    __syncthreads();

    const int tid = blockIdx.x * THREADS + t;
    const int p   = tid * PX_PER_THREAD;       // global pixel index
    const int b   = p >> 16;                   // image index
    const int r   = p & 65535;                 // offset within H*W plane

    const float* tbase = target + (size_t)b * IMG_STRIDE + r;
    const float4 t0lo = *(const float4*)(tbase);
    const float4 t0hi = *(const float4*)(tbase + 4);
    const float4 t1lo = *(const float4*)(tbase + CH_STRIDE);
    const float4 t1hi = *(const float4*)(tbase + CH_STRIDE + 4);

    // pixel pairs packed for f32x2
    unsigned long long T0[4], T1[4];
    T0[0] = pack2f(t0lo.x, t0lo.y);  T0[1] = pack2f(t0lo.z, t0lo.w);
    T0[2] = pack2f(t0hi.x, t0hi.y);  T0[3] = pack2f(t0hi.z, t0hi.w);
    T1[0] = pack2f(t1lo.x, t1lo.y);  T1[1] = pack2f(t1lo.z, t1lo.w);
    T1[2] = pack2f(t1hi.x, t1hi.y);  T1[3] = pack2f(t1hi.z, t1hi.w);

    // best packed (score | index) per pixel; init ~ -FLT_MAX with idx 0
    float bestv[8];
    #pragma unroll
    for (int i = 0; i < 8; i++) bestv[i] = __uint_as_float(0xFF7FFE00u);

    #pragma unroll 4
    for (int k = 0; k < KP; k++) {
        const ulonglong2 c       = sA[k];     // LDS.128: {cx,cx},{cy,cy}
        const unsigned long long cx2  = c.x;
        const unsigned long long cy2  = c.y;
        const unsigned long long bias2 = sB[k];  // LDS.64: {bias,bias}
        #pragma unroll
        for (int j = 0; j < 4; j++) {
            unsigned long long s = ffma2(cx2, T0[j], ffma2(cy2, T1[j], bias2));
            unsigned int slo = (unsigned int)s;
            unsigned int shi = (unsigned int)(s >> 32);
            float flo = __uint_as_float((slo & 0xFFFFFE00u) | (unsigned)k);
            float fhi = __uint_as_float((shi & 0xFFFFFE00u) | (unsigned)k);
            bestv[2 * j]     = fmaxf(bestv[2 * j],     flo);
            bestv[2 * j + 1] = fmaxf(bestv[2 * j + 1], fhi);
        }
    }

    // pred loads + l2 + weighted accumulation (after hot loop: lower reg pressure)
    const float* pbase = pred + (size_t)b * IMG_STRIDE + r;
    const float4 p0lo = *(const float4*)(pbase);
    const float4 p0hi = *(const float4*)(pbase + 4);
    const float4 p1lo = *(const float4*)(pbase + CH_STRIDE);
    const float4 p1hi = *(const float4*)(pbase + CH_STRIDE + 4);

    const float tv0[8] = {t0lo.x, t0lo.y, t0lo.z, t0lo.w, t0hi.x, t0hi.y, t0hi.z, t0hi.w};
    const float tv1[8] = {t1lo.x, t1lo.y, t1lo.z, t1lo.w, t1hi.x, t1hi.y, t1hi.z, t1hi.w};
    const float pv0[8] = {p0lo.x, p0lo.y, p0lo.z, p0lo.w, p0hi.x, p0hi.y, p0hi.z, p0hi.w};
    const float pv1[8] = {p1lo.x, p1lo.y, p1lo.z, p1lo.w, p1hi.x, p1hi.y, p1hi.z, p1hi.w};

    float acc = 0.f;
    #pragma unroll
    for (int i = 0; i < 8; i++) {
        float d0 = pv0[i] - tv0[i];
        float d1 = pv1[i] - tv1[i];
        float l2 = d0 * d0 + d1 * d1;
        unsigned idx = __float_as_uint(bestv[i]) & 0x1FFu;   // <= 319
        acc += l2 * sw_[idx];
    }

    // warp + block reduce (deterministic)
    #pragma unroll
    for (int off = 16; off; off >>= 1)
        acc += __shfl_down_sync(0xFFFFFFFFu, acc, off);
    if ((t & 31) == 0) sred[t >> 5] = acc;
    __syncthreads();
    if (t < THREADS / 32) {
        float v = sred[t];
        #pragma unroll
        for (int off = (THREADS / 64); off; off >>= 1)
            v += __shfl_down_sync(0xFFu, v, off);
        if (t == 0) g_partials[blockIdx.x] = v;
    }
}

__global__ void final_kernel(float* __restrict__ out) {
    __shared__ float s2[NBLOCKS / 32];
    const int t = threadIdx.x;          // NBLOCKS threads
    float v = g_partials[t];
    #pragma unroll
    for (int off = 16; off; off >>= 1)
        v += __shfl_down_sync(0xFFFFFFFFu, v, off);
    if ((t & 31) == 0) s2[t >> 5] = v;
    __syncthreads();
    if (t < NBLOCKS / 32) {
        float x = s2[t];
        #pragma unroll
        for (int off = (NBLOCKS / 64); off; off >>= 1)
            x += __shfl_down_sync(0xFFFFu, x, off);
        if (t == 0) out[0] = x * (1.f / (float)NPIX);
    }
}

extern "C" void kernel_launch(void* const* d_in, const int* in_sizes, int n_in,
                              void* d_out, int out_size) {
    const float* pred    = (const float*)d_in[0];
    const float* target  = (const float*)d_in[1];
    const float* centers = (const float*)d_in[2];
    const float* cw      = (const float*)d_in[3];

    prep_kernel<<<1, KP>>>(centers, cw);
    loss_kernel<<<NBLOCKS, THREADS>>>(pred, target);
    final_kernel<<<1, NBLOCKS>>>((float*)d_out);
}

// round 4
// speedup vs baseline: 3.6031x; 3.6031x over previous
#include <cuda_runtime.h>

// L2LossWithRebalancing — GB300 sm_103a, round 4.
// Exact-Voronoi-LUT design (R3) with the center-load truncation bug fixed:
// K_REAL=313 > 256 threads, so all center loads are strided loops now.

#define K_REAL 313
#define GRIDW 256
#define NCELLS (GRIDW * GRIDW)
#define CAP 16
#define NPIX (16 * 256 * 256)
#define CH_STRIDE 65536
#define IMG_STRIDE 131072
#define LTHREADS 256
#define PXT 4
#define LBLOCKS (NPIX / (LTHREADS * PXT))   // 1024
#define BTHREADS 256
#define BBLOCKS (NCELLS / BTHREADS)         // 256
#define FIXSCALE 1048576.0                  // 2^20

__device__ uint2              g_lut[NCELLS];
__device__ unsigned short     g_cand[NCELLS * CAP];
__device__ float4             g_ctr[K_REAL];   // (2ca, 2cb, -|c|^2, w) denorm coords
__device__ unsigned long long g_acc;           // zero-init; self-resetting
__device__ unsigned int       g_tickets;       // zero-init; self-wrapping

// ---------------------------------------------------------------------------
// Build: one thread per cell. argmin_k d(x,c_k) == argmax_k s_k where
// s_k = 2*c_k.x - |c_k|^2 and d^2 = |x|^2 - s_k.
// Candidate set per cell: d(c_k, cellcenter) <= dmin + sqrt(2) + eps (exact).
// ---------------------------------------------------------------------------
__global__ __launch_bounds__(BTHREADS)
void build_kernel(const float* __restrict__ centers,
                  const float* __restrict__ cw) {
    __shared__ float4 sB[K_REAL];
    const int t = threadIdx.x;
    for (int i = t; i < K_REAL; i += BTHREADS) {          // FIX: strided load
        float ca = centers[2 * i];
        float cb = centers[2 * i + 1];
        float bias = -(ca * ca + cb * cb);
        float w  = cw[i];
        float4 v = make_float4(2.f * ca, 2.f * cb, bias, w);
        sB[i] = v;
        if (blockIdx.x == 0) g_ctr[i] = v;                // FIX: full coverage
    }
    __syncthreads();

    const int cell = blockIdx.x * BTHREADS + t;
    const float ccx = (float)(cell & (GRIDW - 1)) - 127.5f;
    const float ccy = (float)(cell >> 8) - 127.5f;
    const float cc2 = ccx * ccx + ccy * ccy;

    float smax = -1e30f;
    #pragma unroll 4
    for (int k = 0; k < K_REAL; k++) {
        float4 c = sB[k];
        smax = fmaxf(smax, fmaf(c.x, ccx, fmaf(c.y, ccy, c.z)));
    }
    float d2min = fmaxf(cc2 - smax, 0.f);
    float T = sqrtf(d2min) + 1.43421356f;   // sqrt(2) diag + 0.02 fp margin
    T = T * T;
    const float sth = cc2 - T;              // candidate iff s >= sth

    int cnt = 0;
    float w0 = 0.f;
    #pragma unroll 4
    for (int k = 0; k < K_REAL; k++) {
        float4 c = sB[k];
        float s = fmaf(c.x, ccx, fmaf(c.y, ccy, c.z));
        if (s >= sth) {
            if (cnt < CAP) g_cand[cell * CAP + cnt] = (unsigned short)k;
            if (cnt == 0) w0 = c.w;
            cnt++;
        }
    }
    uint2 e;
    if (cnt == 1)        { e.x = __float_as_uint(w0); e.y = 1u; }
    else if (cnt <= CAP) { e.x = 0u; e.y = (unsigned)cnt; }
    else                 { e.x = 0u; e.y = 0xFFFFu; }   // exact full-scan fallback
    g_lut[cell] = e;
}

// ---------------------------------------------------------------------------
// Loss kernel: per-pixel LUT lookup + tiny argmax when needed.
// ---------------------------------------------------------------------------
__global__ __launch_bounds__(LTHREADS)
void loss_kernel(const float* __restrict__ pred,
                 const float* __restrict__ target,
                 float* __restrict__ out) {
    __shared__ float4 sC[K_REAL];
    __shared__ float  sred[LTHREADS / 32];

    const int t = threadIdx.x;
    for (int i = t; i < K_REAL; i += LTHREADS)            // FIX: strided load
        sC[i] = g_ctr[i];
    __syncthreads();

    const int tid = blockIdx.x * LTHREADS + t;
    const int p   = tid * PXT;
    const int b   = p >> 16;
    const int r   = p & 65535;

    const float* tb = target + (size_t)b * IMG_STRIDE + r;
    const float* pb = pred   + (size_t)b * IMG_STRIDE + r;
    const float4 T0 = *(const float4*)tb;
    const float4 T1 = *(const float4*)(tb + CH_STRIDE);
    const float4 P0 = *(const float4*)pb;
    const float4 P1 = *(const float4*)(pb + CH_STRIDE);

    const float f0[4] = {T0.x, T0.y, T0.z, T0.w};
    const float f1[4] = {T1.x, T1.y, T1.z, T1.w};
    const float q0[4] = {P0.x, P0.y, P0.z, P0.w};
    const float q1[4] = {P1.x, P1.y, P1.z, P1.w};

    float acc = 0.f;
    #pragma unroll
    for (int i = 0; i < 4; i++) {
        const float xa = f0[i] * 128.f;                   // denormalized a
        const float xb = f1[i] * 128.f;                   // denormalized b
        int ix = __float2int_rd(xa + 128.f);
        int iy = __float2int_rd(xb + 128.f);
        ix = min(max(ix, 0), GRIDW - 1);
        iy = min(max(iy, 0), GRIDW - 1);
        const int cell = (iy << 8) | ix;
        const uint2 e = __ldg(&g_lut[cell]);

        float w;
        if (e.y == 1u) {
            w = __uint_as_float(e.x);                     // fast path
        } else {
            float bs = -1e30f, bw = 0.f;
            if (e.y <= (unsigned)CAP) {
                const int cnt = (int)e.y;
                const uint4* cp = (const uint4*)&g_cand[cell * CAP];
                const uint4 c8 = __ldg(cp);
                const unsigned ks[8] = {
                    c8.x & 0xFFFFu, c8.x >> 16, c8.y & 0xFFFFu, c8.y >> 16,
                    c8.z & 0xFFFFu, c8.z >> 16, c8.w & 0xFFFFu, c8.w >> 16 };
                #pragma unroll
                for (int j = 0; j < 8; j++) {
                    if (j < cnt) {
                        float4 c = sC[ks[j]];
                        float s = fmaf(c.x, xa, fmaf(c.y, xb, c.z));
                        if (s > bs) { bs = s; bw = c.w; }
                    }
                }
                if (cnt > 8) {
                    const uint4 c8b = __ldg(cp + 1);
                    const unsigned ks2[8] = {
                        c8b.x & 0xFFFFu, c8b.x >> 16, c8b.y & 0xFFFFu, c8b.y >> 16,
                        c8b.z & 0xFFFFu, c8b.z >> 16, c8b.w & 0xFFFFu, c8b.w >> 16 };
                    #pragma unroll
                    for (int j = 0; j < 8; j++) {
                        if (j + 8 < cnt) {
                            float4 c = sC[ks2[j]];
                            float s = fmaf(c.x, xa, fmaf(c.y, xb, c.z));
                            if (s > bs) { bs = s; bw = c.w; }
                        }
                    }
                }
            } else {   // pathological cell: exact full scan
                for (int k = 0; k < K_REAL; k++) {
                    float4 c = sC[k];
                    float s = fmaf(c.x, xa, fmaf(c.y, xb, c.z));
                    if (s > bs) { bs = s; bw = c.w; }
                }
            }
            w = bw;
        }

        const float d0 = q0[i] - f0[i];
        const float d1 = q1[i] - f1[i];
        acc = fmaf(fmaf(d0, d0, d1 * d1), w, acc);
    }

    // deterministic reduction: warp -> block -> fixed-point u64 atomic
    #pragma unroll
    for (int off = 16; off; off >>= 1)
        acc += __shfl_down_sync(0xFFFFFFFFu, acc, off);
    if ((t & 31) == 0) sred[t >> 5] = acc;
    __syncthreads();
    if (t < LTHREADS / 32) {
        float v = sred[t];
        #pragma unroll
        for (int off = (LTHREADS / 64); off; off >>= 1)
            v += __shfl_down_sync(0xFFu, v, off);
        if (t == 0) {
            const unsigned long long fx =
                (unsigned long long)__double2ll_rn((double)v * FIXSCALE);
            atomicAdd(&g_acc, fx);
            __threadfence();
            const unsigned ticket = atomicInc(&g_tickets, LBLOCKS - 1); // wraps
            if (ticket == LBLOCKS - 1) {
                // every other block fenced its add before taking a ticket, so
                // all adds are visible to this ordered read.
                const unsigned long long total = atomicAdd(&g_acc, 0ULL);
                out[0] = (float)((double)total * (1.0 / FIXSCALE / (double)NPIX));
                __threadfence();
                g_acc = 0ULL;                  // reset for next graph replay
            }
        }
    }
}

extern "C" void kernel_launch(void* const* d_in, const int* in_sizes, int n_in,
                              void* d_out, int out_size) {
    const float* pred    = (const float*)d_in[0];
    const float* target  = (const float*)d_in[1];
    const float* centers = (const float*)d_in[2];
    const float* cw      = (const float*)d_in[3];

    build_kernel<<<BBLOCKS, BTHREADS>>>(centers, cw);
    loss_kernel<<<LBLOCKS, LTHREADS>>>(pred, target, (float*)d_out);
}

// round 5
// speedup vs baseline: 3.7826x; 1.0498x over previous
#include <cuda_runtime.h>

// L2LossWithRebalancing — GB300 sm_103a, round 5.
// Exact Voronoi-candidate LUT with INLINE candidate data:
//  - g_lut[cell] = {w, 1} for single-candidate cells (55%+): one 8B load.
//  - g_cdata[cell*8 + j] = (2ca, 2cb, -|c|^2, w): consecutive float4 slots,
//    loaded with full MLP; no index indirection, no shared-memory staging.
//  - cnt > 8 (pathological): exact full scan of g_ctr from L2.
// Loss kernel has no center smem and no setup sync. Deterministic fixed-point
// u64 atomic reduction, self-resetting for graph replay.

#define K_REAL 313
#define GRIDW 256
#define NCELLS (GRIDW * GRIDW)
#define CAPI 8
#define NPIX (16 * 256 * 256)
#define CH_STRIDE 65536
#define IMG_STRIDE 131072
#define LTHREADS 256
#define PXT 4
#define LBLOCKS (NPIX / (LTHREADS * PXT))   // 1024
#define BTHREADS 256
#define BBLOCKS (NCELLS / BTHREADS)         // 256
#define FIXSCALE 1048576.0                  // 2^20

__device__ uint2              g_lut[NCELLS];
__device__ float4             g_cdata[NCELLS * CAPI];   // inline candidate data
__device__ float4             g_ctr[K_REAL];            // (2ca,2cb,-|c|^2,w)
__device__ unsigned long long g_acc;                    // zero-init; self-reset
__device__ unsigned int       g_tickets;                // zero-init; wraps

// ---------------------------------------------------------------------------
// Build: one thread per cell. argmin_k d(x,c_k) == argmax_k s_k,
// s_k = 2*c_k.x - |c_k|^2.  Exact candidate set per cell:
// d(c_k, cellcenter) <= dmin(cc) + sqrt(2) + margin.
// ---------------------------------------------------------------------------
__global__ __launch_bounds__(BTHREADS)
void build_kernel(const float* __restrict__ centers,
                  const float* __restrict__ cw) {
    __shared__ float4 sB[K_REAL];
    const int t = threadIdx.x;
    for (int i = t; i < K_REAL; i += BTHREADS) {
        float ca = centers[2 * i];
        float cb = centers[2 * i + 1];
        float4 v = make_float4(2.f * ca, 2.f * cb,
                               -(ca * ca + cb * cb), cw[i]);
        sB[i] = v;
        if (blockIdx.x == 0) g_ctr[i] = v;
    }
    __syncthreads();

    const int cell = blockIdx.x * BTHREADS + t;
    const float ccx = (float)(cell & (GRIDW - 1)) - 127.5f;
    const float ccy = (float)(cell >> 8) - 127.5f;
    const float cc2 = ccx * ccx + ccy * ccy;

    float smax = -1e30f;
    #pragma unroll 4
    for (int k = 0; k < K_REAL; k++) {
        float4 c = sB[k];
        smax = fmaxf(smax, fmaf(c.x, ccx, fmaf(c.y, ccy, c.z)));
    }
    float d2min = fmaxf(cc2 - smax, 0.f);
    float T = sqrtf(d2min) + 1.43421356f;   // sqrt(2) + 0.02 fp margin
    T = T * T;
    const float sth = cc2 - T;              // candidate iff score >= sth

    int cnt = 0;
    float w0 = 0.f;
    float4* slot = &g_cdata[cell * CAPI];
    #pragma unroll 4
    for (int k = 0; k < K_REAL; k++) {
        float4 c = sB[k];
        float s = fmaf(c.x, ccx, fmaf(c.y, ccy, c.z));
        if (s >= sth) {
            if (cnt < CAPI) slot[cnt] = c;
            if (cnt == 0) w0 = c.w;
            cnt++;
        }
    }
    uint2 e;
    if (cnt == 1)        { e.x = __float_as_uint(w0); e.y = 1u; }
    else if (cnt <= CAPI){ e.x = 0u; e.y = (unsigned)cnt; }
    else                 { e.x = 0u; e.y = 0xFFFFu; }   // full-scan fallback
    g_lut[cell] = e;
}

// ---------------------------------------------------------------------------
// Loss: phase-split per thread (all cells -> all LUT loads -> resolve).
// ---------------------------------------------------------------------------
__global__ __launch_bounds__(LTHREADS)
void loss_kernel(const float* __restrict__ pred,
                 const float* __restrict__ target,
                 float* __restrict__ out) {
    __shared__ float sred[LTHREADS / 32];

    const int t   = threadIdx.x;
    const int tid = blockIdx.x * LTHREADS + t;
    const int p   = tid * PXT;
    const int b   = p >> 16;
    const int r   = p & 65535;

    const float* tb = target + (size_t)b * IMG_STRIDE + r;
    const float* pb = pred   + (size_t)b * IMG_STRIDE + r;
    const float4 T0 = *(const float4*)tb;
    const float4 T1 = *(const float4*)(tb + CH_STRIDE);
    const float4 P0 = *(const float4*)pb;
    const float4 P1 = *(const float4*)(pb + CH_STRIDE);

    const float f0[4] = {T0.x, T0.y, T0.z, T0.w};
    const float f1[4] = {T1.x, T1.y, T1.z, T1.w};
    const float q0[4] = {P0.x, P0.y, P0.z, P0.w};
    const float q1[4] = {P1.x, P1.y, P1.z, P1.w};

    // phase 1: cells + batched LUT loads (maximize MLP)
    int   cells[4];
    uint2 es[4];
    float xa[4], xb[4];
    #pragma unroll
    for (int i = 0; i < 4; i++) {
        xa[i] = f0[i] * 128.f;
        xb[i] = f1[i] * 128.f;
        int ix = __float2int_rd(xa[i] + 128.f);
        int iy = __float2int_rd(xb[i] + 128.f);
        ix = min(max(ix, 0), GRIDW - 1);
        iy = min(max(iy, 0), GRIDW - 1);
        cells[i] = (iy << 8) | ix;
    }
    #pragma unroll
    for (int i = 0; i < 4; i++) es[i] = __ldg(&g_lut[cells[i]]);

    // phase 2: resolve weights + accumulate
    float acc = 0.f;
    #pragma unroll
    for (int i = 0; i < 4; i++) {
        const unsigned cnt = es[i].y;
        float w;
        if (cnt == 1u) {
            w = __uint_as_float(es[i].x);
        } else {
            float bs = -1e30f, bw = 0.f;
            if (cnt <= (unsigned)CAPI) {
                const float4* cd = &g_cdata[cells[i] * CAPI];
                // cnt>=2 here: evaluate 2 unconditionally, rest guarded
                float4 c0 = __ldg(cd + 0);
                float4 c1 = __ldg(cd + 1);
                float s0 = fmaf(c0.x, xa[i], fmaf(c0.y, xb[i], c0.z));
                float s1 = fmaf(c1.x, xa[i], fmaf(c1.y, xb[i], c1.z));
                bs = s0; bw = c0.w;
                if (s1 > bs) { bs = s1; bw = c1.w; }
                #pragma unroll
                for (int j = 2; j < CAPI; j++) {
                    if ((unsigned)j < cnt) {
                        float4 c = __ldg(cd + j);
                        float s = fmaf(c.x, xa[i], fmaf(c.y, xb[i], c.z));
                        if (s > bs) { bs = s; bw = c.w; }
                    }
                }
            } else {   // pathological: exact full scan from L2
                for (int k = 0; k < K_REAL; k++) {
                    float4 c = __ldg(&g_ctr[k]);
                    float s = fmaf(c.x, xa[i], fmaf(c.y, xb[i], c.z));
                    if (s > bs) { bs = s; bw = c.w; }
                }
            }
            w = bw;
        }

        const float d0 = q0[i] - f0[i];
        const float d1 = q1[i] - f1[i];
        acc = fmaf(fmaf(d0, d0, d1 * d1), w, acc);
    }

    // deterministic reduction: warp -> block -> fixed-point u64 atomic
    #pragma unroll
    for (int off = 16; off; off >>= 1)
        acc += __shfl_down_sync(0xFFFFFFFFu, acc, off);
    if ((t & 31) == 0) sred[t >> 5] = acc;
    __syncthreads();
    if (t < LTHREADS / 32) {
        float v = sred[t];
        #pragma unroll
        for (int off = (LTHREADS / 64); off; off >>= 1)
            v += __shfl_down_sync(0xFFu, v, off);
        if (t == 0) {
            const unsigned long long fx =
                (unsigned long long)__double2ll_rn((double)v * FIXSCALE);
            atomicAdd(&g_acc, fx);
            __threadfence();
            const unsigned ticket = atomicInc(&g_tickets, LBLOCKS - 1);
            if (ticket == LBLOCKS - 1) {
                const unsigned long long total = atomicAdd(&g_acc, 0ULL);
                out[0] = (float)((double)total * (1.0 / FIXSCALE / (double)NPIX));
                __threadfence();
                g_acc = 0ULL;                  // reset for next graph replay
            }
        }
    }
}

extern "C" void kernel_launch(void* const* d_in, const int* in_sizes, int n_in,
                              void* d_out, int out_size) {
    const float* pred    = (const float*)d_in[0];
    const float* target  = (const float*)d_in[1];
    const float* centers = (const float*)d_in[2];
    const float* cw      = (const float*)d_in[3];

    build_kernel<<<BBLOCKS, BTHREADS>>>(centers, cw);
    loss_kernel<<<LBLOCKS, LTHREADS>>>(pred, target, (float*)d_out);
}

// round 7
// speedup vs baseline: 5.7442x; 1.5186x over previous
#include <cuda_runtime.h>

// L2LossWithRebalancing — GB300 sm_103a, round 7 (infra retry of R6 with the
// supercell candidate compaction made deterministic via warp-0 ballot).
//
// - Supercell-pruned LUT build: one block per 16x16-cell supercell; warp 0
//   filters centers with d(c,scc) <= dmin(scc)+22.75 (exact cover) into an
//   index-ordered smem list; per-cell passes scan that short list.
// - Loss kernel: 2 pixels/thread (low reg pressure / high occupancy),
//   single-candidate fast path, inline candidate data, exact fallbacks.
// - Deterministic fixed-point u64 atomic reduction, graph-replay safe.

#define K_REAL 313
#define GRIDW 256
#define NCELLS (GRIDW * GRIDW)
#define CAPI 8
#define SCAP 64
#define NPIX (16 * 256 * 256)
#define CH_STRIDE 65536
#define IMG_STRIDE 131072
#define LTHREADS 256
#define PXT 2
#define LBLOCKS (NPIX / (LTHREADS * PXT))   // 2048
#define BTHREADS 256                        // one thread per cell in supercell
#define BBLOCKS 256                         // one block per 16x16 supercell
#define FIXSCALE 1048576.0                  // 2^20

__device__ uint2              g_lut[NCELLS];
__device__ float4             g_cdata[NCELLS * CAPI];   // inline candidates
__device__ float4             g_ctr[K_REAL];            // (2ca,2cb,-|c|^2,w)
__device__ unsigned long long g_acc;                    // zero-init; self-reset
__device__ unsigned int       g_tickets;                // zero-init; wraps

// ---------------------------------------------------------------------------
// Build: block = supercell (16x16 cells), thread = cell.
// score s_k(x) = 2*c_k.x - |c_k|^2 ;  d^2(x,c_k) = |x|^2 - s_k(x).
// ---------------------------------------------------------------------------
__global__ __launch_bounds__(BTHREADS)
void build_kernel(const float* __restrict__ centers,
                  const float* __restrict__ cw) {
    __shared__ float4 sB[K_REAL];
    __shared__ float4 scand[SCAP];
    __shared__ float  swarp[BTHREADS / 32];
    __shared__ float  s_sth;
    __shared__ int    s_cnt;

    const int t = threadIdx.x;
    for (int i = t; i < K_REAL; i += BTHREADS) {
        float ca = centers[2 * i];
        float cb = centers[2 * i + 1];
        float4 v = make_float4(2.f * ca, 2.f * cb,
                               -(ca * ca + cb * cb), cw[i]);
        sB[i] = v;
        if (blockIdx.x == 0) g_ctr[i] = v;
    }
    __syncthreads();

    // supercell center
    const int sx = blockIdx.x & 15;
    const int sy = blockIdx.x >> 4;
    const float sccx = 16.f * sx - 120.f;
    const float sccy = 16.f * sy - 120.f;
    const float scc2 = sccx * sccx + sccy * sccy;

    // block-cooperative max score at scc
    float m = -1e30f;
    for (int i = t; i < K_REAL; i += BTHREADS) {
        float4 c = sB[i];
        m = fmaxf(m, fmaf(c.x, sccx, fmaf(c.y, sccy, c.z)));
    }
    #pragma unroll
    for (int off = 16; off; off >>= 1)
        m = fmaxf(m, __shfl_xor_sync(0xFFFFFFFFu, m, off));
    if ((t & 31) == 0) swarp[t >> 5] = m;
    __syncthreads();
    if (t == 0) {
        float mm = swarp[0];
        #pragma unroll
        for (int wnum = 1; wnum < BTHREADS / 32; wnum++)
            mm = fmaxf(mm, swarp[wnum]);
        float d2min = fmaxf(scc2 - mm, 0.f);
        float T = sqrtf(d2min) + 22.75f;   // 2*7.5*sqrt2 + sqrt2 + margin
        s_sth = scc2 - T * T;              // supercell candidate iff s >= this
    }
    __syncthreads();

    // DETERMINISTIC candidate compaction: warp 0 only, index-ordered.
    if (t < 32) {
        const float sth_sc = s_sth;
        int cnt = 0;
        for (int base = 0; base < K_REAL; base += 32) {
            const int i = base + t;
            bool pred = false;
            float4 c = make_float4(0.f, 0.f, 0.f, 0.f);
            if (i < K_REAL) {
                c = sB[i];
                pred = (fmaf(c.x, sccx, fmaf(c.y, sccy, c.z)) >= sth_sc);
            }
            const unsigned mask = __ballot_sync(0xFFFFFFFFu, pred);
            if (pred) {
                const int pos = cnt + __popc(mask & ((1u << t) - 1u));
                if (pos < SCAP) scand[pos] = c;
            }
            cnt += __popc(mask);
        }
        if (t == 0) s_cnt = cnt;
    }
    __syncthreads();

    const float4* list;
    int n;
    if (s_cnt <= SCAP) { list = scand; n = s_cnt; }
    else               { list = sB;    n = K_REAL; }   // overflow fallback

    // per-cell passes over the (small) list
    const int ix = 16 * sx + (t & 15);
    const int iy = 16 * sy + (t >> 4);
    const float ccx = (float)ix - 127.5f;
    const float ccy = (float)iy - 127.5f;
    const float cc2 = ccx * ccx + ccy * ccy;

    float smax = -1e30f;
    for (int k = 0; k < n; k++) {
        float4 c = list[k];
        smax = fmaxf(smax, fmaf(c.x, ccx, fmaf(c.y, ccy, c.z)));
    }
    float d2min = fmaxf(cc2 - smax, 0.f);
    float T = sqrtf(d2min) + 1.43421356f;  // sqrt(2) diag + fp margin
    const float sth = cc2 - T * T;

    const int cell = (iy << 8) | ix;
    int cnt = 0;
    float w0 = 0.f;
    float4* slot = &g_cdata[cell * CAPI];
    for (int k = 0; k < n; k++) {
        float4 c = list[k];
        float s = fmaf(c.x, ccx, fmaf(c.y, ccy, c.z));
        if (s >= sth) {
            if (cnt < CAPI) slot[cnt] = c;
            if (cnt == 0) w0 = c.w;
            cnt++;
        }
    }
    uint2 e;
    if (cnt == 1)         { e.x = __float_as_uint(w0); e.y = 1u; }
    else if (cnt <= CAPI) { e.x = 0u; e.y = (unsigned)cnt; }
    else                  { e.x = 0u; e.y = 0xFFFFu; }   // loss full-scan
    g_lut[cell] = e;
}

// ---------------------------------------------------------------------------
// Loss: 2 pixels/thread (occupancy-first), LUT lookup + tiny inline argmax.
// ---------------------------------------------------------------------------
__global__ __launch_bounds__(LTHREADS)
void loss_kernel(const float* __restrict__ pred,
                 const float* __restrict__ target,
                 float* __restrict__ out) {
    __shared__ float sred[LTHREADS / 32];

    const int t   = threadIdx.x;
    const int tid = blockIdx.x * LTHREADS + t;
    const int p   = tid * PXT;
    const int b   = p >> 16;
    const int r   = p & 65535;

    const float* tb = target + (size_t)b * IMG_STRIDE + r;
    const float* pb = pred   + (size_t)b * IMG_STRIDE + r;
    const float2 T0 = *(const float2*)tb;
    const float2 T1 = *(const float2*)(tb + CH_STRIDE);
    const float2 P0 = *(const float2*)pb;
    const float2 P1 = *(const float2*)(pb + CH_STRIDE);

    const float f0[2] = {T0.x, T0.y};
    const float f1[2] = {T1.x, T1.y};
    const float q0[2] = {P0.x, P0.y};
    const float q1[2] = {P1.x, P1.y};

    // cells + batched LUT loads
    int   cells[2];
    uint2 es[2];
    float xa[2], xb[2];
    #pragma unroll
    for (int i = 0; i < 2; i++) {
        xa[i] = f0[i] * 128.f;
        xb[i] = f1[i] * 128.f;
        int ix = __float2int_rd(xa[i] + 128.f);
        int iy = __float2int_rd(xb[i] + 128.f);
        ix = min(max(ix, 0), GRIDW - 1);
        iy = min(max(iy, 0), GRIDW - 1);
        cells[i] = (iy << 8) | ix;
    }
    #pragma unroll
    for (int i = 0; i < 2; i++) es[i] = __ldg(&g_lut[cells[i]]);

    float acc = 0.f;
    #pragma unroll
    for (int i = 0; i < 2; i++) {
        const unsigned cnt = es[i].y;
        float w;
        if (cnt == 1u) {
            w = __uint_as_float(es[i].x);
        } else {
            float bs = -1e30f, bw = 0.f;
            if (cnt <= (unsigned)CAPI) {
                const float4* cd = &g_cdata[cells[i] * CAPI];
                float4 c0 = __ldg(cd + 0);
                float4 c1 = __ldg(cd + 1);
                float s0 = fmaf(c0.x, xa[i], fmaf(c0.y, xb[i], c0.z));
                float s1 = fmaf(c1.x, xa[i], fmaf(c1.y, xb[i], c1.z));
                bs = s0; bw = c0.w;
                if (s1 > bs) { bs = s1; bw = c1.w; }
                #pragma unroll
                for (int j = 2; j < CAPI; j++) {
                    if ((unsigned)j < cnt) {
                        float4 c = __ldg(cd + j);
                        float s = fmaf(c.x, xa[i], fmaf(c.y, xb[i], c.z));
                        if (s > bs) { bs = s; bw = c.w; }
                    }
                }
            } else {   // pathological: exact full scan from L2
                for (int k = 0; k < K_REAL; k++) {
                    float4 c = __ldg(&g_ctr[k]);
                    float s = fmaf(c.x, xa[i], fmaf(c.y, xb[i], c.z));
                    if (s > bs) { bs = s; bw = c.w; }
                }
            }
            w = bw;
        }

        const float d0 = q0[i] - f0[i];
        const float d1 = q1[i] - f1[i];
        acc = fmaf(fmaf(d0, d0, d1 * d1), w, acc);
    }

    // deterministic reduction: warp -> block -> fixed-point u64 atomic
    #pragma unroll
    for (int off = 16; off; off >>= 1)
        acc += __shfl_down_sync(0xFFFFFFFFu, acc, off);
    if ((t & 31) == 0) sred[t >> 5] = acc;
    __syncthreads();
    if (t < LTHREADS / 32) {
        float v = sred[t];
        #pragma unroll
        for (int off = (LTHREADS / 64); off; off >>= 1)
            v += __shfl_down_sync(0xFFu, v, off);
        if (t == 0) {
            const unsigned long long fx =
                (unsigned long long)__double2ll_rn((double)v * FIXSCALE);
            atomicAdd(&g_acc, fx);
            __threadfence();
            const unsigned ticket = atomicInc(&g_tickets, LBLOCKS - 1);
            if (ticket == LBLOCKS - 1) {
                const unsigned long long total = atomicAdd(&g_acc, 0ULL);
                out[0] = (float)((double)total * (1.0 / FIXSCALE / (double)NPIX));
                __threadfence();
                g_acc = 0ULL;                  // reset for next graph replay
            }
        }
    }
}

extern "C" void kernel_launch(void* const* d_in, const int* in_sizes, int n_in,
                              void* d_out, int out_size) {
    const float* pred    = (const float*)d_in[0];
    const float* target  = (const float*)d_in[1];
    const float* centers = (const float*)d_in[2];
    const float* cw      = (const float*)d_in[3];

    build_kernel<<<BBLOCKS, BTHREADS>>>(centers, cw);
    loss_kernel<<<LBLOCKS, LTHREADS>>>(pred, target, (float*)d_out);
}